// round 1
// baseline (speedup 1.0000x reference)
#include <cuda_runtime.h>
#include <math.h>

#define HH 256
#define NDIM 64
#define LFULL 2048
#define LH 1025   // L/2 + 1

// ---- device scratch (no allocations allowed) ----
__device__ float4 g_v0[HH * NDIM];   // v00r v00i v01r v01i   (scaled by dt)
__device__ float4 g_v1[HH * NDIM];   // v10r v10i v11  0      (scaled by dt)
__device__ float2 g_w [HH * NDIM];   // wdt (complex)
__device__ float2 g_kf[HH * LH];     // k_f spectrum

// ============================================================
// Kernel 1: per (h,n) parameter prep.  S == H so rep == 1.
// v00 = B*C, v01 = B*conj(P), v10 = P*C, v11 = |P|^2, all * dt
// wdt = (-exp(inv_w_real) + i*w_imag) * dt
// ============================================================
__global__ void prep_kernel(const float* __restrict__ C, const float* __restrict__ B,
                            const float* __restrict__ P, const float* __restrict__ iwr,
                            const float* __restrict__ wim, const float* __restrict__ logdt)
{
    int idx = blockIdx.x * blockDim.x + threadIdx.x;
    if (idx >= HH * NDIM) return;
    int h = idx / NDIM;

    float dt = expf(logdt[h]);
    float wr = -expf(iwr[idx]) * dt;
    float wi = wim[idx] * dt;

    float Cr = C[2*idx], Ci = C[2*idx + 1];
    float Br = B[2*idx], Bi = B[2*idx + 1];
    float Pr = P[2*idx], Pi = P[2*idx + 1];

    float v00r = Br*Cr - Bi*Ci,  v00i = Br*Ci + Bi*Cr;
    float v01r = Br*Pr + Bi*Pi,  v01i = Bi*Pr - Br*Pi;   // B * conj(P)
    float v10r = Pr*Cr - Pi*Ci,  v10i = Pr*Ci + Pi*Cr;
    float v11  = Pr*Pr + Pi*Pi;                          // P * conj(P), real

    g_v0[idx] = make_float4(v00r*dt, v00i*dt, v01r*dt, v01i*dt);
    g_v1[idx] = make_float4(v10r*dt, v10i*dt, v11*dt, 0.0f);
    g_w [idx] = make_float2(wr, wi);
}

// ============================================================
// Kernel 2: Cauchy sums (with conjugate-pair extension) + Woodbury.
// One block per (h, l-chunk). Per-h params in shared (broadcast reads).
// r_ab = S1_ab + conj(S2_ab);  S1 = sum v/(z-w),  S2 = sum v/(conj(z)-w)
// k_f  = (r00 - r01*r10/(1+r11)) * 2/(1+omega)
// ============================================================
__global__ __launch_bounds__(256)
void cauchy_kernel()
{
    __shared__ float4 sv0[NDIM];
    __shared__ float4 sv1[NDIM];
    __shared__ float2 sw [NDIM];

    const int h   = blockIdx.x;
    const int tid = threadIdx.x;
    if (tid < NDIM) {
        sv0[tid] = g_v0[h * NDIM + tid];
        sv1[tid] = g_v1[h * NDIM + tid];
        sw [tid] = g_w [h * NDIM + tid];
    }
    __syncthreads();

    const int l = blockIdx.y * blockDim.x + tid;
    if (l >= LH) return;

    // --- per-l setup in double (NaN-safe at l = L/2 where 1+omega ~ 1e-7) ---
    const float w0f = (float)(6.283185307179586476925286766559 / (double)LFULL);
    float thetaf = w0f * (float)l;            // matches jnp's fp32 angle
    double th = (double)thetaf;
    double sd = sin(th), cd = cos(th);
    double omr = cd, omi = -sd;               // omega = exp(-i*theta)
    double denr = 1.0 + omr, deni = omi;      // 1 + omega
    double dinv = 1.0 / (denr*denr + deni*deni);
    double numr = 1.0 - omr, numi = -omi;     // 1 - omega
    float zr = (float)(2.0 * (numr*denr + numi*deni) * dinv);
    float zi = (float)(2.0 * (numi*denr - numr*deni) * dinv);
    float fr = (float)( 2.0 * denr * dinv);   // 2/(1+omega)
    float fi = (float)(-2.0 * deni * dinv);

    float a00r=0.f,a00i=0.f,a01r=0.f,a01i=0.f,a10r=0.f,a10i=0.f,a11r=0.f,a11i=0.f;
    float b00r=0.f,b00i=0.f,b01r=0.f,b01i=0.f,b10r=0.f,b10i=0.f,b11r=0.f,b11i=0.f;

    #pragma unroll 8
    for (int n = 0; n < NDIM; n++) {
        float4 v0 = sv0[n];
        float4 v1 = sv1[n];
        float2 w  = sw [n];
        float dr  = zr - w.x;
        float drq = dr * dr;

        // denominator 1: z - w
        float di  = zi - w.y;
        float inv = 1.0f / (drq + di*di);
        float tr  = dr * inv, ti = -di * inv;
        a00r += v0.x*tr - v0.y*ti;   a00i += v0.x*ti + v0.y*tr;
        a01r += v0.z*tr - v0.w*ti;   a01i += v0.z*ti + v0.w*tr;
        a10r += v1.x*tr - v1.y*ti;   a10i += v1.x*ti + v1.y*tr;
        a11r += v1.z*tr;             a11i += v1.z*ti;

        // denominator 2: conj(z) - w  (shares dr)
        float di2  = -zi - w.y;
        float inv2 = 1.0f / (drq + di2*di2);
        float tr2  = dr * inv2, ti2 = -di2 * inv2;
        b00r += v0.x*tr2 - v0.y*ti2; b00i += v0.x*ti2 + v0.y*tr2;
        b01r += v0.z*tr2 - v0.w*ti2; b01i += v0.z*ti2 + v0.w*tr2;
        b10r += v1.x*tr2 - v1.y*ti2; b10i += v1.x*ti2 + v1.y*tr2;
        b11r += v1.z*tr2;            b11i += v1.z*ti2;
    }

    // r = S1 + conj(S2)
    float r00r = a00r + b00r, r00i = a00i - b00i;
    float r01r = a01r + b01r, r01i = a01i - b01i;
    float r10r = a10r + b10r, r10i = a10i - b10i;
    float r11r = a11r + b11r, r11i = a11i - b11i;

    // Woodbury: k = r00 - r01*r10/(1+r11)
    float d11r = 1.0f + r11r, d11i = r11i;
    float dinv11 = 1.0f / (d11r*d11r + d11i*d11i);
    float nr = r01r*r10r - r01i*r10i;
    float ni = r01r*r10i + r01i*r10r;
    float qr = (nr*d11r + ni*d11i) * dinv11;
    float qi = (ni*d11r - nr*d11i) * dinv11;
    float kr = r00r - qr, ki = r00i - qi;

    // * 2/(1+omega)
    float kfr = kr*fr - ki*fi;
    float kfi = kr*fi + ki*fr;
    g_kf[h * LH + l] = make_float2(kfr, kfi);
}

// ============================================================
// Kernel 3: irfft(L=2048) per h via shared-memory radix-2 iFFT.
// Hermitian extension -> bit-reverse -> 11 DIT stages -> real/L.
// ============================================================
__global__ __launch_bounds__(256)
void ifft_kernel(float* __restrict__ out)
{
    __shared__ float2 X[LFULL];
    const int h   = blockIdx.x;
    const int tid = threadIdx.x;

    // Hermitian-extend half spectrum to full length
    for (int i = tid; i < LFULL; i += 256) {
        float2 v;
        if (i <= LFULL/2) {
            v = g_kf[h * LH + i];
        } else {
            float2 t = g_kf[h * LH + (LFULL - i)];
            v = make_float2(t.x, -t.y);
        }
        X[i] = v;
    }
    __syncthreads();

    // bit-reversal (11 bits)
    for (int i = tid; i < LFULL; i += 256) {
        int j = __brev(i) >> 21;
        if (i < j) { float2 t = X[i]; X[i] = X[j]; X[j] = t; }
    }
    __syncthreads();

    // inverse DIT stages (twiddle sign +)
    for (int st = 0; st < 11; st++) {
        int half = 1 << st;
        int len  = half << 1;
        float ang = 6.28318530717958647693f / (float)len;
        for (int b = tid; b < LFULL/2; b += 256) {
            int j    = b & (half - 1);
            int base = (b >> st) << (st + 1);
            float sj, cj;
            sincosf(ang * (float)j, &sj, &cj);
            float2 u = X[base + j];
            float2 v = X[base + j + half];
            float vr = v.x*cj - v.y*sj;
            float vi = v.x*sj + v.y*cj;
            X[base + j]        = make_float2(u.x + vr, u.y + vi);
            X[base + j + half] = make_float2(u.x - vr, u.y - vi);
        }
        __syncthreads();
    }

    const float sc = 1.0f / (float)LFULL;
    for (int i = tid; i < LFULL; i += 256)
        out[h * LFULL + i] = X[i].x * sc;
}

// ============================================================
extern "C" void kernel_launch(void* const* d_in, const int* in_sizes, int n_in,
                              void* d_out, int out_size)
{
    const float* C     = (const float*)d_in[0];   // (1,256,64,2)
    const float* B     = (const float*)d_in[1];   // (1,256,64,2)
    const float* P     = (const float*)d_in[2];   // (1,256,64,2)
    const float* iwr   = (const float*)d_in[3];   // (256,64)
    const float* wim   = (const float*)d_in[4];   // (256,64)
    const float* logdt = (const float*)d_in[5];   // (256,)
    (void)in_sizes; (void)n_in; (void)out_size;

    prep_kernel<<<(HH * NDIM + 255) / 256, 256>>>(C, B, P, iwr, wim, logdt);

    dim3 g2(HH, (LH + 255) / 256);   // 256 x 5 blocks
    cauchy_kernel<<<g2, 256>>>();

    ifft_kernel<<<HH, 256>>>((float*)d_out);
}

// round 2
// speedup vs baseline: 1.1083x; 1.1083x over previous
#include <cuda_runtime.h>
#include <math.h>

#define HH 256
#define NDIM 64
#define LFULL 2048
#define LH 1025   // L/2 + 1

// ---- device scratch (no allocations allowed) ----
__device__ float2 g_z [LH];          // bilinear node z(l)
__device__ float2 g_f [LH];          // final factor 2/(1+omega)
__device__ float2 g_kf[HH * LH];     // k_f spectrum

// ================= f32x2 packed helpers =================
typedef unsigned long long ull;

__device__ __forceinline__ ull f2pack(float lo, float hi) {
    ull r; asm("mov.b64 %0, {%1,%2};" : "=l"(r) : "f"(lo), "f"(hi)); return r;
}
__device__ __forceinline__ void f2unpack(ull v, float& lo, float& hi) {
    asm("mov.b64 {%0,%1}, %2;" : "=f"(lo), "=f"(hi) : "l"(v));
}
__device__ __forceinline__ ull f2add(ull a, ull b) {
    ull r; asm("add.rn.f32x2 %0, %1, %2;" : "=l"(r) : "l"(a), "l"(b)); return r;
}
__device__ __forceinline__ ull f2mul(ull a, ull b) {
    ull r; asm("mul.rn.f32x2 %0, %1, %2;" : "=l"(r) : "l"(a), "l"(b)); return r;
}
__device__ __forceinline__ ull f2fma(ull a, ull b, ull c) {
    ull r; asm("fma.rn.f32x2 %0, %1, %2, %3;" : "=l"(r) : "l"(a), "l"(b), "l"(c)); return r;
}
__device__ __forceinline__ float frcp(float x) {
    float r; asm("rcp.approx.f32 %0, %1;" : "=f"(r) : "f"(x)); return r;
}

// ============================================================
// Kernel 0: per-l z / f setup in double (NaN-safe at l=L/2).
// Tiny: 1025 threads total; removes 256x-redundant DP work.
// ============================================================
__global__ void setup_kernel()
{
    int l = blockIdx.x * blockDim.x + threadIdx.x;
    if (l >= LH) return;
    const float w0f = (float)(6.283185307179586476925286766559 / (double)LFULL);
    float thetaf = w0f * (float)l;           // match jnp's fp32 angle
    double th = (double)thetaf;
    double sd = sin(th), cd = cos(th);
    double omr = cd, omi = -sd;              // omega = exp(-i*theta)
    double denr = 1.0 + omr, deni = omi;     // 1 + omega
    double dinv = 1.0 / (denr*denr + deni*deni);
    double numr = 1.0 - omr, numi = -omi;    // 1 - omega
    g_z[l] = make_float2((float)(2.0 * (numr*denr + numi*deni) * dinv),
                         (float)(2.0 * (numi*denr - numr*deni) * dinv));
    g_f[l] = make_float2((float)( 2.0 * denr * dinv),
                         (float)(-2.0 * deni * dinv));
}

// ============================================================
// Kernel 1: fused prep + Cauchy + Woodbury, f32x2 packed.
// Lane 0 = denominator (z - w), lane 1 = (conj(z) - w); they
// share dr. r_ab = S_lane0 + conj(S_lane1).
// ============================================================
__global__ __launch_bounds__(256)
void cauchy_kernel(const float* __restrict__ C, const float* __restrict__ B,
                   const float* __restrict__ P, const float* __restrict__ iwr,
                   const float* __restrict__ wim, const float* __restrict__ logdt)
{
    // duplicated-value layout so LDS.128 delivers broadcast f32x2 packs
    __shared__ ulonglong2 sW  [NDIM];  // (-wr,-wr | -wi,-wi)
    __shared__ ulonglong2 sV00[NDIM];  // (v00r,v00r | v00i,v00i)
    __shared__ ulonglong2 sV01[NDIM];
    __shared__ ulonglong2 sV10[NDIM];
    __shared__ ull        sV11[NDIM];  // (v11,v11)

    const int h   = blockIdx.x;
    const int tid = threadIdx.x;

    if (tid < NDIM) {
        int idx = h * NDIM + tid;
        float dt = expf(logdt[h]);
        float wr = -expf(iwr[idx]) * dt;
        float wi = wim[idx] * dt;

        float Cr = C[2*idx], Ci = C[2*idx + 1];
        float Br = B[2*idx], Bi = B[2*idx + 1];
        float Pr = P[2*idx], Pi = P[2*idx + 1];

        float v00r = (Br*Cr - Bi*Ci) * dt,  v00i = (Br*Ci + Bi*Cr) * dt;
        float v01r = (Br*Pr + Bi*Pi) * dt,  v01i = (Bi*Pr - Br*Pi) * dt;  // B*conj(P)
        float v10r = (Pr*Cr - Pi*Ci) * dt,  v10i = (Pr*Ci + Pi*Cr) * dt;
        float v11  = (Pr*Pr + Pi*Pi) * dt;                                // |P|^2

        float* p;
        p = (float*)&sW  [tid]; p[0]=p[1]=-wr;   p[2]=p[3]=-wi;
        p = (float*)&sV00[tid]; p[0]=p[1]=v00r;  p[2]=p[3]=v00i;
        p = (float*)&sV01[tid]; p[0]=p[1]=v01r;  p[2]=p[3]=v01i;
        p = (float*)&sV10[tid]; p[0]=p[1]=v10r;  p[2]=p[3]=v10i;
        p = (float*)&sV11[tid]; p[0]=p[1]=v11;
    }
    __syncthreads();

    const int l = blockIdx.y * blockDim.x + tid;
    if (l >= LH) return;

    float2 z = g_z[l];
    const ull zr2 = f2pack(z.x,  z.x);
    const ull zi2 = f2pack(z.y, -z.y);

    // accumulators (packed over the two denominators)
    ull ar00=0, s1_00=0, s2_00=0;   // real; vi*tr; vr*ti
    ull ar01=0, s1_01=0, s2_01=0;
    ull ar10=0, s1_10=0, s2_10=0;
    ull p11=0, q11=0;

    #pragma unroll 8
    for (int n = 0; n < NDIM; n++) {
        ulonglong2 w = sW[n];
        ull dr = f2add(zr2, w.x);
        ull di = f2add(zi2, w.y);
        ull d2 = f2fma(di, di, f2mul(dr, dr));

        float lo, hi;
        f2unpack(d2, lo, hi);
        float rc = frcp(lo * hi);
        ull inv = f2pack(hi * rc, lo * rc);

        ull tr = f2mul(dr, inv);
        ull ti = f2mul(di, inv);

        ulonglong2 v0 = sV00[n];
        ar00 = f2fma(v0.x, tr, ar00);  ar00 = f2fma(v0.y, ti, ar00);
        s1_00 = f2fma(v0.y, tr, s1_00); s2_00 = f2fma(v0.x, ti, s2_00);

        ulonglong2 v1 = sV01[n];
        ar01 = f2fma(v1.x, tr, ar01);  ar01 = f2fma(v1.y, ti, ar01);
        s1_01 = f2fma(v1.y, tr, s1_01); s2_01 = f2fma(v1.x, ti, s2_01);

        ulonglong2 v2 = sV10[n];
        ar10 = f2fma(v2.x, tr, ar10);  ar10 = f2fma(v2.y, ti, ar10);
        s1_10 = f2fma(v2.y, tr, s1_10); s2_10 = f2fma(v2.x, ti, s2_10);

        ull v3 = sV11[n];
        p11 = f2fma(v3, tr, p11);
        q11 = f2fma(v3, ti, q11);
    }

    // combine lanes: r = S_lane0 + conj(S_lane1); imag_lane = s1 - s2
    float a, b, c, d;
    f2unpack(ar00, a, b);  float r00r = a + b;
    f2unpack(s1_00, a, b); f2unpack(s2_00, c, d);
    float r00i = (a - c) - (b - d);

    f2unpack(ar01, a, b);  float r01r = a + b;
    f2unpack(s1_01, a, b); f2unpack(s2_01, c, d);
    float r01i = (a - c) - (b - d);

    f2unpack(ar10, a, b);  float r10r = a + b;
    f2unpack(s1_10, a, b); f2unpack(s2_10, c, d);
    float r10i = (a - c) - (b - d);

    f2unpack(p11, a, b);   float r11r = a + b;
    f2unpack(q11, a, b);   float r11i = b - a;

    // Woodbury: k = r00 - r01*r10/(1+r11)
    float d11r = 1.0f + r11r, d11i = r11i;
    float dinv11 = 1.0f / (d11r*d11r + d11i*d11i);
    float nr = r01r*r10r - r01i*r10i;
    float ni = r01r*r10i + r01i*r10r;
    float qr = (nr*d11r + ni*d11i) * dinv11;
    float qi = (ni*d11r - nr*d11i) * dinv11;
    float kr = r00r - qr, ki = r00i - qi;

    // * 2/(1+omega)
    float2 f = g_f[l];
    g_kf[h * LH + l] = make_float2(kr*f.x - ki*f.y, kr*f.y + ki*f.x);
}

// ============================================================
// Kernel 2: irfft(L=2048) per h, shared-memory radix-2 iFFT
// with a precomputed twiddle table (no per-butterfly sincosf).
// ============================================================
__global__ __launch_bounds__(256)
void ifft_kernel(float* __restrict__ out)
{
    __shared__ float2 X[LFULL];
    __shared__ float2 tw[LFULL / 2];   // tw[m] = exp(+i*2*pi*m/L)
    const int h   = blockIdx.x;
    const int tid = threadIdx.x;

    const float ang0 = 6.28318530717958647693f / (float)LFULL;
    for (int m = tid; m < LFULL/2; m += 256) {
        float s, c; sincosf(ang0 * (float)m, &s, &c);
        tw[m] = make_float2(c, s);
    }

    // Hermitian-extend half spectrum to full length
    for (int i = tid; i < LFULL; i += 256) {
        float2 v;
        if (i <= LFULL/2) {
            v = g_kf[h * LH + i];
        } else {
            float2 t = g_kf[h * LH + (LFULL - i)];
            v = make_float2(t.x, -t.y);
        }
        X[i] = v;
    }
    __syncthreads();

    // bit-reversal (11 bits)
    for (int i = tid; i < LFULL; i += 256) {
        int j = __brev(i) >> 21;
        if (i < j) { float2 t = X[i]; X[i] = X[j]; X[j] = t; }
    }
    __syncthreads();

    // inverse DIT stages (twiddle sign +)
    for (int st = 0; st < 11; st++) {
        int half  = 1 << st;
        int shift = 10 - st;
        for (int b = tid; b < LFULL/2; b += 256) {
            int j    = b & (half - 1);
            int base = (b >> st) << (st + 1);
            float2 w = tw[j << shift];
            float2 u = X[base + j];
            float2 v = X[base + j + half];
            float vr = v.x*w.x - v.y*w.y;
            float vi = v.x*w.y + v.y*w.x;
            X[base + j]        = make_float2(u.x + vr, u.y + vi);
            X[base + j + half] = make_float2(u.x - vr, u.y - vi);
        }
        __syncthreads();
    }

    const float sc = 1.0f / (float)LFULL;
    for (int i = tid; i < LFULL; i += 256)
        out[h * LFULL + i] = X[i].x * sc;
}

// ============================================================
extern "C" void kernel_launch(void* const* d_in, const int* in_sizes, int n_in,
                              void* d_out, int out_size)
{
    const float* C     = (const float*)d_in[0];   // (1,256,64,2)
    const float* B     = (const float*)d_in[1];   // (1,256,64,2)
    const float* P     = (const float*)d_in[2];   // (1,256,64,2)
    const float* iwr   = (const float*)d_in[3];   // (256,64)
    const float* wim   = (const float*)d_in[4];   // (256,64)
    const float* logdt = (const float*)d_in[5];   // (256,)
    (void)in_sizes; (void)n_in; (void)out_size;

    setup_kernel<<<(LH + 255) / 256, 256>>>();

    dim3 g2(HH, (LH + 255) / 256);   // 256 x 5 blocks
    cauchy_kernel<<<g2, 256>>>(C, B, P, iwr, wim, logdt);

    ifft_kernel<<<HH, 256>>>((float*)d_out);
}

// round 3
// speedup vs baseline: 1.4095x; 1.2718x over previous
#include <cuda_runtime.h>
#include <math.h>

#define HH 256
#define NDIM 64
#define LFULL 2048
#define LH 1025   // L/2 + 1
#define LHP 1026  // padded stride (even -> float4-aligned pair stores)

// ---- device scratch (no allocations allowed) ----
__device__ float2 g_kf[HH * LHP];

// ================= f32x2 packed helpers =================
typedef unsigned long long ull;

__device__ __forceinline__ ull f2pack(float lo, float hi) {
    ull r; asm("mov.b64 %0, {%1,%2};" : "=l"(r) : "f"(lo), "f"(hi)); return r;
}
__device__ __forceinline__ void f2unpack(ull v, float& lo, float& hi) {
    asm("mov.b64 {%0,%1}, %2;" : "=f"(lo), "=f"(hi) : "l"(v));
}
__device__ __forceinline__ ull f2add(ull a, ull b) {
    ull r; asm("add.rn.f32x2 %0, %1, %2;" : "=l"(r) : "l"(a), "l"(b)); return r;
}
__device__ __forceinline__ ull f2mul(ull a, ull b) {
    ull r; asm("mul.rn.f32x2 %0, %1, %2;" : "=l"(r) : "l"(a), "l"(b)); return r;
}
__device__ __forceinline__ ull f2fma(ull a, ull b, ull c) {
    ull r; asm("fma.rn.f32x2 %0, %1, %2, %3;" : "=l"(r) : "l"(a), "l"(b), "l"(c)); return r;
}
__device__ __forceinline__ float frcp(float x) {
    float r; asm("rcp.approx.f32 %0, %1;" : "=f"(r) : "f"(x)); return r;
}

// ============================================================
// Fused prep + Cauchy + Woodbury.
// Conjugate pair combined analytically:
//   v/(z-w) + conj(v)/(z-conj(w)) = (bv + i*av*y) / ((dw - y^2) + i*cw*y)
// with z = i*y, y = 2*tan(theta/2), all coefficients real.
// f32x2 lanes carry TWO adjacent l values.
// ============================================================
__global__ __launch_bounds__(192)
void cauchy_kernel(const float* __restrict__ C, const float* __restrict__ B,
                   const float* __restrict__ P, const float* __restrict__ iwr,
                   const float* __restrict__ wim, const float* __restrict__ logdt)
{
    __shared__ ulonglong2 sW [NDIM];   // (cw,cw | dw,dw)
    __shared__ ulonglong2 sV0[NDIM];   // (av00,av00 | bv00,bv00)
    __shared__ ulonglong2 sV1[NDIM];   // v01 = B*conj(P)
    __shared__ ulonglong2 sV2[NDIM];   // v10 = P*C
    __shared__ ulonglong2 sV3[NDIM];   // v11 = |P|^2

    const int h   = blockIdx.x;
    const int tid = threadIdx.x;

    if (tid < NDIM) {
        int idx = h * NDIM + tid;
        float dt = expf(logdt[h]);
        float wr = -expf(iwr[idx]) * dt;
        float wi = wim[idx] * dt;

        float Cr = C[2*idx], Ci = C[2*idx + 1];
        float Br = B[2*idx], Bi = B[2*idx + 1];
        float Pr = P[2*idx], Pi = P[2*idx + 1];

        // v * dt
        float v00r = (Br*Cr - Bi*Ci) * dt,  v00i = (Br*Ci + Bi*Cr) * dt;
        float v01r = (Br*Pr + Bi*Pi) * dt,  v01i = (Bi*Pr - Br*Pi) * dt;  // B*conj(P)
        float v10r = (Pr*Cr - Pi*Ci) * dt,  v10i = (Pr*Ci + Pi*Cr) * dt;
        float v11r = (Pr*Pr + Pi*Pi) * dt;                                // real

        float cw = -2.0f * wr;
        float dw = wr*wr + wi*wi;

        float* q;
        q = (float*)&sW [tid]; q[0]=q[1]=cw; q[2]=q[3]=dw;
        q = (float*)&sV0[tid]; q[0]=q[1]=2.0f*v00r; q[2]=q[3]=-2.0f*(v00r*wr + v00i*wi);
        q = (float*)&sV1[tid]; q[0]=q[1]=2.0f*v01r; q[2]=q[3]=-2.0f*(v01r*wr + v01i*wi);
        q = (float*)&sV2[tid]; q[0]=q[1]=2.0f*v10r; q[2]=q[3]=-2.0f*(v10r*wr + v10i*wi);
        q = (float*)&sV3[tid]; q[0]=q[1]=2.0f*v11r; q[2]=q[3]=-2.0f*(v11r*wr);
    }
    __syncthreads();

    const int p = blockIdx.y * 192 + tid;   // pair index; lanes = (2p, 2p+1)
    if (p > 512) return;
    const int l0 = 2 * p;

    // y = 2*tan(theta/2); half-angle step = pi/L (exactly half of fp32 2pi/L)
    const float hw = (float)(3.1415926535897932384626433832795 / (double)LFULL);
    float y0 = 2.0f * tanf(hw * (float)l0);
    float y1 = 2.0f * tanf(hw * (float)(l0 + 1));

    const ull Y   = f2pack(y0, y1);
    const ull NY2 = f2pack(-y0*y0, -y1*y1);
    const ull ONE  = f2pack(1.0f, 1.0f);
    const ull NEG1 = f2pack(-1.0f, -1.0f);
    const ull HALF = f2pack(0.5f, 0.5f);

    ull A0=0,B0=0,C0=0,D0=0;   // A=sum av*tr, B=sum av*ti, C=sum bv*tr, D=sum bv*ti
    ull A1=0,B1=0,C1=0,D1=0;
    ull A2=0,B2=0,C2=0,D2=0;
    ull A3=0,B3=0,C3=0,D3=0;

    #pragma unroll 8
    for (int n = 0; n < NDIM; n++) {
        ulonglong2 W = sW[n];
        ull er = f2add(W.y, NY2);                 // dw - y^2
        ull ei = f2mul(W.x, Y);                   // cw * y
        ull d2 = f2fma(ei, ei, f2mul(er, er));
        float lo, hi; f2unpack(d2, lo, hi);
        ull inv = f2pack(frcp(lo), frcp(hi));
        ull tr = f2mul(er, inv);
        ull ti = f2mul(ei, inv);

        ulonglong2 v;
        v = sV0[n];
        A0 = f2fma(v.x, tr, A0); B0 = f2fma(v.x, ti, B0);
        C0 = f2fma(v.y, tr, C0); D0 = f2fma(v.y, ti, D0);
        v = sV1[n];
        A1 = f2fma(v.x, tr, A1); B1 = f2fma(v.x, ti, B1);
        C1 = f2fma(v.y, tr, C1); D1 = f2fma(v.y, ti, D1);
        v = sV2[n];
        A2 = f2fma(v.x, tr, A2); B2 = f2fma(v.x, ti, B2);
        C2 = f2fma(v.y, tr, C2); D2 = f2fma(v.y, ti, D2);
        v = sV3[n];
        A3 = f2fma(v.x, tr, A3); B3 = f2fma(v.x, ti, B3);
        C3 = f2fma(v.y, tr, C3); D3 = f2fma(v.y, ti, D3);
    }

    // r = (C + y*B) + i*(y*A - D)
    ull r00r = f2fma(Y, B0, C0), r00i = f2fma(Y, A0, f2mul(NEG1, D0));
    ull r01r = f2fma(Y, B1, C1), r01i = f2fma(Y, A1, f2mul(NEG1, D1));
    ull r10r = f2fma(Y, B2, C2), r10i = f2fma(Y, A2, f2mul(NEG1, D2));
    ull r11r = f2fma(Y, B3, C3), r11i = f2fma(Y, A3, f2mul(NEG1, D3));

    // Woodbury: k = r00 - r01*r10/(1+r11)
    ull d11r = f2add(ONE, r11r);
    ull d11i = r11i;
    ull den  = f2fma(d11i, d11i, f2mul(d11r, d11r));
    float dlo, dhi; f2unpack(den, dlo, dhi);
    ull dinv = f2pack(frcp(dlo), frcp(dhi));
    ull t  = f2mul(r01i, r10i);
    ull nr = f2fma(r01r, r10r, f2mul(NEG1, t));
    ull ni = f2fma(r01r, r10i, f2mul(r01i, r10r));
    ull qr = f2mul(f2fma(ni, d11i, f2mul(nr, d11r)), dinv);
    ull qi = f2mul(f2fma(ni, d11r, f2mul(NEG1, f2mul(nr, d11i))), dinv);
    ull kr = f2fma(NEG1, qr, r00r);
    ull ki = f2fma(NEG1, qi, r00i);

    // * (1 + i*y/2)
    ull Y2  = f2mul(Y, HALF);
    ull kfr = f2fma(NEG1, f2mul(Y2, ki), kr);
    ull kfi = f2fma(Y2, kr, ki);

    float kr0, kr1, ki0, ki1;
    f2unpack(kfr, kr0, kr1);
    f2unpack(kfi, ki0, ki1);

    if (l0 < 1024) {
        *(float4*)&g_kf[h * LHP + l0] = make_float4(kr0, ki0, kr1, ki1);
    } else { // l0 == 1024: only lane0 valid
        g_kf[h * LHP + 1024] = make_float2(kr0, ki0);
    }
}

// ============================================================
// irfft(L=2048) per h: shared-memory radix-2 iFFT + twiddle table.
// ============================================================
__global__ __launch_bounds__(256)
void ifft_kernel(float* __restrict__ out)
{
    __shared__ float2 X[LFULL];
    __shared__ float2 tw[LFULL / 2];   // tw[m] = exp(+i*2*pi*m/L)
    const int h   = blockIdx.x;
    const int tid = threadIdx.x;

    const float ang0 = 6.28318530717958647693f / (float)LFULL;
    for (int m = tid; m < LFULL/2; m += 256) {
        float s, c; sincosf(ang0 * (float)m, &s, &c);
        tw[m] = make_float2(c, s);
    }

    for (int i = tid; i < LFULL; i += 256) {
        float2 v;
        if (i <= LFULL/2) {
            v = g_kf[h * LHP + i];
        } else {
            float2 t = g_kf[h * LHP + (LFULL - i)];
            v = make_float2(t.x, -t.y);
        }
        X[i] = v;
    }
    __syncthreads();

    for (int i = tid; i < LFULL; i += 256) {
        int j = __brev(i) >> 21;
        if (i < j) { float2 t = X[i]; X[i] = X[j]; X[j] = t; }
    }
    __syncthreads();

    for (int st = 0; st < 11; st++) {
        int half  = 1 << st;
        int shift = 10 - st;
        for (int b = tid; b < LFULL/2; b += 256) {
            int j    = b & (half - 1);
            int base = (b >> st) << (st + 1);
            float2 w = tw[j << shift];
            float2 u = X[base + j];
            float2 v = X[base + j + half];
            float vr = v.x*w.x - v.y*w.y;
            float vi = v.x*w.y + v.y*w.x;
            X[base + j]        = make_float2(u.x + vr, u.y + vi);
            X[base + j + half] = make_float2(u.x - vr, u.y - vi);
        }
        __syncthreads();
    }

    const float sc = 1.0f / (float)LFULL;
    for (int i = tid; i < LFULL; i += 256)
        out[h * LFULL + i] = X[i].x * sc;
}

// ============================================================
extern "C" void kernel_launch(void* const* d_in, const int* in_sizes, int n_in,
                              void* d_out, int out_size)
{
    const float* C     = (const float*)d_in[0];   // (1,256,64,2)
    const float* B     = (const float*)d_in[1];   // (1,256,64,2)
    const float* P     = (const float*)d_in[2];   // (1,256,64,2)
    const float* iwr   = (const float*)d_in[3];   // (256,64)
    const float* wim   = (const float*)d_in[4];   // (256,64)
    const float* logdt = (const float*)d_in[5];   // (256,)
    (void)in_sizes; (void)n_in; (void)out_size;

    dim3 g2(HH, 3);   // 3 * 192 = 576 pairs >= 513
    cauchy_kernel<<<g2, 192>>>(C, B, P, iwr, wim, logdt);

    ifft_kernel<<<HH, 256>>>((float*)d_out);
}

// round 5
// speedup vs baseline: 2.0411x; 1.4481x over previous
#include <cuda_runtime.h>
#include <math.h>

#define HH 256
#define NDIM 64
#define LFULL 2048
#define M1024 1024

// ================= f32x2 packed helpers =================
typedef unsigned long long ull;

__device__ __forceinline__ ull f2pack(float lo, float hi) {
    ull r; asm("mov.b64 %0, {%1,%2};" : "=l"(r) : "f"(lo), "f"(hi)); return r;
}
__device__ __forceinline__ void f2unpack(ull v, float& lo, float& hi) {
    asm("mov.b64 {%0,%1}, %2;" : "=f"(lo), "=f"(hi) : "l"(v));
}
__device__ __forceinline__ ull f2add(ull a, ull b) {
    ull r; asm("add.rn.f32x2 %0, %1, %2;" : "=l"(r) : "l"(a), "l"(b)); return r;
}
__device__ __forceinline__ ull f2mul(ull a, ull b) {
    ull r; asm("mul.rn.f32x2 %0, %1, %2;" : "=l"(r) : "l"(a), "l"(b)); return r;
}
__device__ __forceinline__ ull f2fma(ull a, ull b, ull c) {
    ull r; asm("fma.rn.f32x2 %0, %1, %2, %3;" : "=l"(r) : "l"(a), "l"(b), "l"(c)); return r;
}
__device__ __forceinline__ float frcp(float x) {
    float r; asm("rcp.approx.f32 %0, %1;" : "=f"(r) : "f"(x)); return r;
}
__device__ __forceinline__ float2 cmul(float2 a, float2 b) {
    return make_float2(a.x*b.x - a.y*b.y, a.x*b.y + a.y*b.x);
}

// ============================================================
// Fully fused: prep + Cauchy/Woodbury (f32x2, conj-pair folded)
// + real-packed half-size radix-4 inverse FFT. One block per h.
// Pair 512 (l=1024) handled cooperatively by warp 0 (no straggler).
// ============================================================
__global__ __launch_bounds__(256)
void fused_kernel(const float* __restrict__ C, const float* __restrict__ B,
                  const float* __restrict__ P, const float* __restrict__ iwr,
                  const float* __restrict__ wim, const float* __restrict__ logdt,
                  float* __restrict__ out)
{
    __shared__ ulonglong2 sW [NDIM];   // (cw,cw | dw,dw)
    __shared__ ulonglong2 sV0[NDIM];   // (av,av | bv,bv) for v00
    __shared__ ulonglong2 sV1[NDIM];   // v01
    __shared__ ulonglong2 sV2[NDIM];   // v10
    __shared__ ulonglong2 sV3[NDIM];   // v11
    __shared__ float2 skf[1026];       // k_f[0..1024]
    __shared__ __align__(16) float2 X[M1024];  // FFT workspace
    __shared__ float2 tw[256];         // tw[m] = exp(+i*2*pi*m/1024)

    const int h   = blockIdx.x;
    const int tid = threadIdx.x;

    // ---------- phase 0: parameter prep ----------
    if (tid < NDIM) {
        int idx = h * NDIM + tid;
        float dt = expf(logdt[h]);
        float wr = -expf(iwr[idx]) * dt;
        float wi = wim[idx] * dt;

        float Cr = C[2*idx], Ci = C[2*idx + 1];
        float Br = B[2*idx], Bi = B[2*idx + 1];
        float Pr = P[2*idx], Pi = P[2*idx + 1];

        float v00r = (Br*Cr - Bi*Ci) * dt,  v00i = (Br*Ci + Bi*Cr) * dt;
        float v01r = (Br*Pr + Bi*Pi) * dt,  v01i = (Bi*Pr - Br*Pi) * dt;  // B*conj(P)
        float v10r = (Pr*Cr - Pi*Ci) * dt,  v10i = (Pr*Ci + Pi*Cr) * dt;
        float v11r = (Pr*Pr + Pi*Pi) * dt;

        float cw = -2.0f * wr;
        float dw = wr*wr + wi*wi;

        float* q;
        q = (float*)&sW [tid]; q[0]=q[1]=cw; q[2]=q[3]=dw;
        q = (float*)&sV0[tid]; q[0]=q[1]=2.0f*v00r; q[2]=q[3]=-2.0f*(v00r*wr + v00i*wi);
        q = (float*)&sV1[tid]; q[0]=q[1]=2.0f*v01r; q[2]=q[3]=-2.0f*(v01r*wr + v01i*wi);
        q = (float*)&sV2[tid]; q[0]=q[1]=2.0f*v10r; q[2]=q[3]=-2.0f*(v10r*wr + v10i*wi);
        q = (float*)&sV3[tid]; q[0]=q[1]=2.0f*v11r; q[2]=q[3]=-2.0f*(v11r*wr);
    }
    // twiddle table fill (independent of phase 0 data)
    {
        float s, c;
        sincosf((float)(6.283185307179586 / 1024.0) * (float)tid, &s, &c);
        tw[tid] = make_float2(c, s);
    }
    __syncthreads();

    const float hw = (float)(3.1415926535897932384626433832795 / (double)LFULL);

    // ---------- phase 1a: pairs 0..511, two per thread ----------
    #pragma unroll
    for (int pk = 0; pk < 2; pk++) {
        const int p  = tid + pk * 256;
        const int l0 = 2 * p;

        float y0 = 2.0f * tanf(hw * (float)l0);
        float y1 = 2.0f * tanf(hw * (float)(l0 + 1));

        const ull Y    = f2pack(y0, y1);
        const ull NY2  = f2pack(-y0*y0, -y1*y1);
        const ull ONE  = f2pack(1.0f, 1.0f);
        const ull NEG1 = f2pack(-1.0f, -1.0f);
        const ull HALF = f2pack(0.5f, 0.5f);

        ull A0=0,B0=0,C0=0,D0=0;
        ull A1=0,B1=0,C1=0,D1=0;
        ull A2=0,B2=0,C2=0,D2=0;
        ull A3=0,B3=0,C3=0,D3=0;

        #pragma unroll 8
        for (int n = 0; n < NDIM; n++) {
            ulonglong2 W = sW[n];
            ull er = f2add(W.y, NY2);                 // dw - y^2
            ull ei = f2mul(W.x, Y);                   // cw * y
            ull d2 = f2fma(ei, ei, f2mul(er, er));
            float lo, hi; f2unpack(d2, lo, hi);
            ull inv = f2pack(frcp(lo), frcp(hi));
            ull tr = f2mul(er, inv);
            ull ti = f2mul(ei, inv);

            ulonglong2 v;
            v = sV0[n];
            A0 = f2fma(v.x, tr, A0); B0 = f2fma(v.x, ti, B0);
            C0 = f2fma(v.y, tr, C0); D0 = f2fma(v.y, ti, D0);
            v = sV1[n];
            A1 = f2fma(v.x, tr, A1); B1 = f2fma(v.x, ti, B1);
            C1 = f2fma(v.y, tr, C1); D1 = f2fma(v.y, ti, D1);
            v = sV2[n];
            A2 = f2fma(v.x, tr, A2); B2 = f2fma(v.x, ti, B2);
            C2 = f2fma(v.y, tr, C2); D2 = f2fma(v.y, ti, D2);
            v = sV3[n];
            A3 = f2fma(v.x, tr, A3); B3 = f2fma(v.x, ti, B3);
            C3 = f2fma(v.y, tr, C3); D3 = f2fma(v.y, ti, D3);
        }

        // r = (C + y*B) + i*(y*A - D)
        ull r00r = f2fma(Y, B0, C0), r00i = f2fma(Y, A0, f2mul(NEG1, D0));
        ull r01r = f2fma(Y, B1, C1), r01i = f2fma(Y, A1, f2mul(NEG1, D1));
        ull r10r = f2fma(Y, B2, C2), r10i = f2fma(Y, A2, f2mul(NEG1, D2));
        ull r11r = f2fma(Y, B3, C3), r11i = f2fma(Y, A3, f2mul(NEG1, D3));

        // Woodbury: k = r00 - r01*r10/(1+r11)
        ull d11r = f2add(ONE, r11r);
        ull d11i = r11i;
        ull den  = f2fma(d11i, d11i, f2mul(d11r, d11r));
        float dlo, dhi; f2unpack(den, dlo, dhi);
        ull dinv = f2pack(frcp(dlo), frcp(dhi));
        ull t2 = f2mul(r01i, r10i);
        ull nr = f2fma(r01r, r10r, f2mul(NEG1, t2));
        ull ni = f2fma(r01r, r10i, f2mul(r01i, r10r));
        ull qr = f2mul(f2fma(ni, d11i, f2mul(nr, d11r)), dinv);
        ull qi = f2mul(f2fma(ni, d11r, f2mul(NEG1, f2mul(nr, d11i))), dinv);
        ull kr = f2fma(NEG1, qr, r00r);
        ull ki = f2fma(NEG1, qi, r00i);

        // * (1 + i*y/2)
        ull Y2  = f2mul(Y, HALF);
        ull kfr = f2fma(NEG1, f2mul(Y2, ki), kr);
        ull kfi = f2fma(Y2, kr, ki);

        float kr0, kr1, ki0, ki1;
        f2unpack(kfr, kr0, kr1);
        f2unpack(kfi, ki0, ki1);

        skf[l0]     = make_float2(kr0, ki0);
        skf[l0 + 1] = make_float2(kr1, ki1);
    }

    // ---------- phase 1b: pair 512 (l = 1024) by warp 0 cooperatively ----------
    if (tid < 32) {
        const float y = 2.0f * tanf(hw * 1024.0f);
        const float ny2 = -y * y;
        float A0=0.f,B0=0.f,C0=0.f,D0=0.f;
        float A1=0.f,B1=0.f,C1=0.f,D1=0.f;
        float A2=0.f,B2=0.f,C2=0.f,D2=0.f;
        float A3=0.f,B3=0.f,C3=0.f,D3=0.f;

        #pragma unroll
        for (int k = 0; k < 2; k++) {
            int n = tid + k * 32;
            const float* W = (const float*)&sW[n];
            float er = W[2] + ny2;        // dw - y^2
            float ei = W[0] * y;          // cw * y
            float inv = frcp(er*er + ei*ei);
            float tr = er * inv, ti = ei * inv;
            const float* v;
            v = (const float*)&sV0[n];
            A0 += v[0]*tr; B0 += v[0]*ti; C0 += v[2]*tr; D0 += v[2]*ti;
            v = (const float*)&sV1[n];
            A1 += v[0]*tr; B1 += v[0]*ti; C1 += v[2]*tr; D1 += v[2]*ti;
            v = (const float*)&sV2[n];
            A2 += v[0]*tr; B2 += v[0]*ti; C2 += v[2]*tr; D2 += v[2]*ti;
            v = (const float*)&sV3[n];
            A3 += v[0]*tr; B3 += v[0]*ti; C3 += v[2]*tr; D3 += v[2]*ti;
        }
        // warp butterfly reduction of 16 accumulators
        #pragma unroll
        for (int off = 16; off > 0; off >>= 1) {
            A0 += __shfl_xor_sync(0xffffffffu, A0, off);
            B0 += __shfl_xor_sync(0xffffffffu, B0, off);
            C0 += __shfl_xor_sync(0xffffffffu, C0, off);
            D0 += __shfl_xor_sync(0xffffffffu, D0, off);
            A1 += __shfl_xor_sync(0xffffffffu, A1, off);
            B1 += __shfl_xor_sync(0xffffffffu, B1, off);
            C1 += __shfl_xor_sync(0xffffffffu, C1, off);
            D1 += __shfl_xor_sync(0xffffffffu, D1, off);
            A2 += __shfl_xor_sync(0xffffffffu, A2, off);
            B2 += __shfl_xor_sync(0xffffffffu, B2, off);
            C2 += __shfl_xor_sync(0xffffffffu, C2, off);
            D2 += __shfl_xor_sync(0xffffffffu, D2, off);
            A3 += __shfl_xor_sync(0xffffffffu, A3, off);
            B3 += __shfl_xor_sync(0xffffffffu, B3, off);
            C3 += __shfl_xor_sync(0xffffffffu, C3, off);
            D3 += __shfl_xor_sync(0xffffffffu, D3, off);
        }
        if (tid == 0) {
            float r00r = C0 + y*B0, r00i = y*A0 - D0;
            float r01r = C1 + y*B1, r01i = y*A1 - D1;
            float r10r = C2 + y*B2, r10i = y*A2 - D2;
            float r11r = C3 + y*B3, r11i = y*A3 - D3;
            float d11r = 1.0f + r11r, d11i = r11i;
            float dinv = frcp(d11r*d11r + d11i*d11i);
            float nr = r01r*r10r - r01i*r10i;
            float ni = r01r*r10i + r01i*r10r;
            float qr = (nr*d11r + ni*d11i) * dinv;
            float qi = (ni*d11r - nr*d11i) * dinv;
            float kr = r00r - qr, ki = r00i - qi;
            float y2 = 0.5f * y;
            skf[1024] = make_float2(kr - y2*ki, ki + y2*kr);
        }
    }
    __syncthreads();

    // ---------- phase 2: build Z (real-packed half-size spectrum) ----------
    // Z[m] = E + i*O; E=(K[m]+conj(K[M-m]))/2, O=e^{+i*pi*m/1024}*(K[m]-conj(K[M-m]))/2
    #pragma unroll
    for (int m = tid; m < M1024; m += 256) {
        float2 Ka = skf[m];
        float2 Kb = skf[M1024 - m];
        float Er = 0.5f * (Ka.x + Kb.x);
        float Ei = 0.5f * (Ka.y - Kb.y);
        float Fr = 0.5f * (Ka.x - Kb.x);
        float Fi = 0.5f * (Ka.y + Kb.y);
        float s, c;
        sincosf((float)(3.141592653589793 / 1024.0) * (float)m, &s, &c);
        float Or = c*Fr - s*Fi;
        float Oi = c*Fi + s*Fr;
        X[m] = make_float2(Er - Oi, Ei + Or);
    }
    __syncthreads();

    // ---------- phase 3: base-4 digit reversal (10 bits) ----------
    #pragma unroll
    for (int i = tid; i < M1024; i += 256) {
        unsigned r = __brev((unsigned)i) >> 22;
        r = ((r & 0x155u) << 1) | ((r >> 1) & 0x155u);
        if ((int)r > i) { float2 tswap = X[i]; X[i] = X[r]; X[r] = tswap; }
    }
    __syncthreads();

    // ---------- phase 4: 5 radix-4 DIT stages (inverse: +i) ----------
    {
        float4 lo4 = *(const float4*)&X[4*tid];
        float4 hi4 = *(const float4*)&X[4*tid + 2];
        float2 a = make_float2(lo4.x, lo4.y), b = make_float2(lo4.z, lo4.w);
        float2 c = make_float2(hi4.x, hi4.y), d = make_float2(hi4.z, hi4.w);
        float2 apc = make_float2(a.x+c.x, a.y+c.y), amc = make_float2(a.x-c.x, a.y-c.y);
        float2 bpd = make_float2(b.x+d.x, b.y+d.y), bmd = make_float2(b.x-d.x, b.y-d.y);
        float2 y0 = make_float2(apc.x+bpd.x, apc.y+bpd.y);
        float2 y1 = make_float2(amc.x-bmd.y, amc.y+bmd.x);
        float2 y2 = make_float2(apc.x-bpd.x, apc.y-bpd.y);
        float2 y3 = make_float2(amc.x+bmd.y, amc.y-bmd.x);
        *(float4*)&X[4*tid]     = make_float4(y0.x, y0.y, y1.x, y1.y);
        *(float4*)&X[4*tid + 2] = make_float4(y2.x, y2.y, y3.x, y3.y);
    }
    __syncthreads();

    #pragma unroll
    for (int st = 1; st < 5; st++) {
        int q = 1 << (2*st);
        int j = tid & (q - 1);
        int i0 = ((tid >> (2*st)) << (2*st + 2)) + j;
        float2 w1 = tw[j << (2*(4 - st))];
        float2 w2 = cmul(w1, w1);
        float2 w3 = cmul(w2, w1);

        float2 a = X[i0];
        float2 b = cmul(X[i0 + q],   w1);
        float2 c = cmul(X[i0 + 2*q], w2);
        float2 d = cmul(X[i0 + 3*q], w3);
        float2 apc = make_float2(a.x+c.x, a.y+c.y), amc = make_float2(a.x-c.x, a.y-c.y);
        float2 bpd = make_float2(b.x+d.x, b.y+d.y), bmd = make_float2(b.x-d.x, b.y-d.y);
        X[i0]       = make_float2(apc.x+bpd.x, apc.y+bpd.y);
        X[i0 + q]   = make_float2(amc.x-bmd.y, amc.y+bmd.x);
        X[i0 + 2*q] = make_float2(apc.x-bpd.x, apc.y-bpd.y);
        X[i0 + 3*q] = make_float2(amc.x+bmd.y, amc.y-bmd.x);
        __syncthreads();
    }

    // ---------- phase 5: unpack to real output ----------
    const float sc = 1.0f / 1024.0f;
    float2* out2 = (float2*)(out + h * LFULL);
    #pragma unroll
    for (int t = tid; t < M1024; t += 256) {
        float2 z = X[t];
        out2[t] = make_float2(z.x * sc, z.y * sc);
    }
}

// ============================================================
extern "C" void kernel_launch(void* const* d_in, const int* in_sizes, int n_in,
                              void* d_out, int out_size)
{
    const float* C     = (const float*)d_in[0];   // (1,256,64,2)
    const float* B     = (const float*)d_in[1];   // (1,256,64,2)
    const float* P     = (const float*)d_in[2];   // (1,256,64,2)
    const float* iwr   = (const float*)d_in[3];   // (256,64)
    const float* wim   = (const float*)d_in[4];   // (256,64)
    const float* logdt = (const float*)d_in[5];   // (256,)
    (void)in_sizes; (void)n_in; (void)out_size;

    fused_kernel<<<HH, 256>>>(C, B, P, iwr, wim, logdt, (float*)d_out);
}

// round 6
// speedup vs baseline: 2.1921x; 1.0740x over previous
#include <cuda_runtime.h>
#include <math.h>

#define HH 256
#define NDIM 64
#define LFULL 2048
#define M1024 1024
#define NT 512

// ================= f32x2 packed helpers =================
typedef unsigned long long ull;

__device__ __forceinline__ ull f2pack(float lo, float hi) {
    ull r; asm("mov.b64 %0, {%1,%2};" : "=l"(r) : "f"(lo), "f"(hi)); return r;
}
__device__ __forceinline__ void f2unpack(ull v, float& lo, float& hi) {
    asm("mov.b64 {%0,%1}, %2;" : "=f"(lo), "=f"(hi) : "l"(v));
}
__device__ __forceinline__ ull f2add(ull a, ull b) {
    ull r; asm("add.rn.f32x2 %0, %1, %2;" : "=l"(r) : "l"(a), "l"(b)); return r;
}
__device__ __forceinline__ ull f2mul(ull a, ull b) {
    ull r; asm("mul.rn.f32x2 %0, %1, %2;" : "=l"(r) : "l"(a), "l"(b)); return r;
}
__device__ __forceinline__ ull f2fma(ull a, ull b, ull c) {
    ull r; asm("fma.rn.f32x2 %0, %1, %2, %3;" : "=l"(r) : "l"(a), "l"(b), "l"(c)); return r;
}
__device__ __forceinline__ float frcp(float x) {
    float r; asm("rcp.approx.f32 %0, %1;" : "=f"(r) : "f"(x)); return r;
}
__device__ __forceinline__ float2 cmul(float2 a, float2 b) {
    return make_float2(a.x*b.x - a.y*b.y, a.x*b.y + a.y*b.x);
}

// ============================================================
// Fully fused: prep + Cauchy/Woodbury (f32x2) + real-packed
// half-size radix-4 inverse FFT. One block of 512 threads per h;
// each thread owns exactly ONE l-pair (2x warps vs R5 -> hides
// the RCP/LDS latency chain). Pair 512 done by warp 0 co-op.
// ============================================================
__global__ __launch_bounds__(NT)
void fused_kernel(const float* __restrict__ C, const float* __restrict__ B,
                  const float* __restrict__ P, const float* __restrict__ iwr,
                  const float* __restrict__ wim, const float* __restrict__ logdt,
                  float* __restrict__ out)
{
    __shared__ ulonglong2 sW [NDIM];   // (cw,cw | dw,dw)
    __shared__ ulonglong2 sV0[NDIM];   // (av,av | bv,bv) for v00
    __shared__ ulonglong2 sV1[NDIM];   // v01
    __shared__ ulonglong2 sV2[NDIM];   // v10
    __shared__ ulonglong2 sV3[NDIM];   // v11
    __shared__ float2 skf[1026];       // k_f[0..1024]
    __shared__ __align__(16) float2 X[M1024];  // FFT workspace
    __shared__ float2 tw[256];         // tw[m] = exp(+i*2*pi*m/1024)

    const int h   = blockIdx.x;
    const int tid = threadIdx.x;

    // ---------- phase 0: parameter prep ----------
    if (tid < NDIM) {
        int idx = h * NDIM + tid;
        float dt = expf(logdt[h]);
        float wr = -expf(iwr[idx]) * dt;
        float wi = wim[idx] * dt;

        float Cr = C[2*idx], Ci = C[2*idx + 1];
        float Br = B[2*idx], Bi = B[2*idx + 1];
        float Pr = P[2*idx], Pi = P[2*idx + 1];

        float v00r = (Br*Cr - Bi*Ci) * dt,  v00i = (Br*Ci + Bi*Cr) * dt;
        float v01r = (Br*Pr + Bi*Pi) * dt,  v01i = (Bi*Pr - Br*Pi) * dt;  // B*conj(P)
        float v10r = (Pr*Cr - Pi*Ci) * dt,  v10i = (Pr*Ci + Pi*Cr) * dt;
        float v11r = (Pr*Pr + Pi*Pi) * dt;

        float cw = -2.0f * wr;
        float dw = wr*wr + wi*wi;

        float* q;
        q = (float*)&sW [tid]; q[0]=q[1]=cw; q[2]=q[3]=dw;
        q = (float*)&sV0[tid]; q[0]=q[1]=2.0f*v00r; q[2]=q[3]=-2.0f*(v00r*wr + v00i*wi);
        q = (float*)&sV1[tid]; q[0]=q[1]=2.0f*v01r; q[2]=q[3]=-2.0f*(v01r*wr + v01i*wi);
        q = (float*)&sV2[tid]; q[0]=q[1]=2.0f*v10r; q[2]=q[3]=-2.0f*(v10r*wr + v10i*wi);
        q = (float*)&sV3[tid]; q[0]=q[1]=2.0f*v11r; q[2]=q[3]=-2.0f*(v11r*wr);
    }
    // twiddle table fill
    if (tid >= 256 && tid < 512) {
        int m = tid - 256;
        float s, c;
        sincosf((float)(6.283185307179586 / 1024.0) * (float)m, &s, &c);
        tw[m] = make_float2(c, s);
    }
    __syncthreads();

    const float hw = (float)(3.1415926535897932384626433832795 / (double)LFULL);

    // ---------- phase 1a: one pair-pack per thread (pairs 0..511) ----------
    {
        const int l0 = 2 * tid;

        float y0 = 2.0f * tanf(hw * (float)l0);
        float y1 = 2.0f * tanf(hw * (float)(l0 + 1));

        const ull Y    = f2pack(y0, y1);
        const ull NY2  = f2pack(-y0*y0, -y1*y1);
        const ull ONE  = f2pack(1.0f, 1.0f);
        const ull NEG1 = f2pack(-1.0f, -1.0f);
        const ull HALF = f2pack(0.5f, 0.5f);

        ull A0=0,B0=0,C0=0,D0=0;
        ull A1=0,B1=0,C1=0,D1=0;
        ull A2=0,B2=0,C2=0,D2=0;
        ull A3=0,B3=0,C3=0,D3=0;

        #pragma unroll 8
        for (int n = 0; n < NDIM; n++) {
            ulonglong2 W = sW[n];
            ull er = f2add(W.y, NY2);                 // dw - y^2
            ull ei = f2mul(W.x, Y);                   // cw * y
            ull d2 = f2fma(ei, ei, f2mul(er, er));
            float lo, hi; f2unpack(d2, lo, hi);
            ull inv = f2pack(frcp(lo), frcp(hi));
            ull tr = f2mul(er, inv);
            ull ti = f2mul(ei, inv);

            ulonglong2 v;
            v = sV0[n];
            A0 = f2fma(v.x, tr, A0); B0 = f2fma(v.x, ti, B0);
            C0 = f2fma(v.y, tr, C0); D0 = f2fma(v.y, ti, D0);
            v = sV1[n];
            A1 = f2fma(v.x, tr, A1); B1 = f2fma(v.x, ti, B1);
            C1 = f2fma(v.y, tr, C1); D1 = f2fma(v.y, ti, D1);
            v = sV2[n];
            A2 = f2fma(v.x, tr, A2); B2 = f2fma(v.x, ti, B2);
            C2 = f2fma(v.y, tr, C2); D2 = f2fma(v.y, ti, D2);
            v = sV3[n];
            A3 = f2fma(v.x, tr, A3); B3 = f2fma(v.x, ti, B3);
            C3 = f2fma(v.y, tr, C3); D3 = f2fma(v.y, ti, D3);
        }

        // r = (C + y*B) + i*(y*A - D)
        ull r00r = f2fma(Y, B0, C0), r00i = f2fma(Y, A0, f2mul(NEG1, D0));
        ull r01r = f2fma(Y, B1, C1), r01i = f2fma(Y, A1, f2mul(NEG1, D1));
        ull r10r = f2fma(Y, B2, C2), r10i = f2fma(Y, A2, f2mul(NEG1, D2));
        ull r11r = f2fma(Y, B3, C3), r11i = f2fma(Y, A3, f2mul(NEG1, D3));

        // Woodbury: k = r00 - r01*r10/(1+r11)
        ull d11r = f2add(ONE, r11r);
        ull d11i = r11i;
        ull den  = f2fma(d11i, d11i, f2mul(d11r, d11r));
        float dlo, dhi; f2unpack(den, dlo, dhi);
        ull dinv = f2pack(frcp(dlo), frcp(dhi));
        ull t2 = f2mul(r01i, r10i);
        ull nr = f2fma(r01r, r10r, f2mul(NEG1, t2));
        ull ni = f2fma(r01r, r10i, f2mul(r01i, r10r));
        ull qr = f2mul(f2fma(ni, d11i, f2mul(nr, d11r)), dinv);
        ull qi = f2mul(f2fma(ni, d11r, f2mul(NEG1, f2mul(nr, d11i))), dinv);
        ull kr = f2fma(NEG1, qr, r00r);
        ull ki = f2fma(NEG1, qi, r00i);

        // * (1 + i*y/2)
        ull Y2  = f2mul(Y, HALF);
        ull kfr = f2fma(NEG1, f2mul(Y2, ki), kr);
        ull kfi = f2fma(Y2, kr, ki);

        float kr0, kr1, ki0, ki1;
        f2unpack(kfr, kr0, kr1);
        f2unpack(kfi, ki0, ki1);

        skf[l0]     = make_float2(kr0, ki0);
        skf[l0 + 1] = make_float2(kr1, ki1);
    }

    // ---------- phase 1b: pair 512 (l = 1024) by warp 0 cooperatively ----------
    if (tid < 32) {
        const float y = 2.0f * tanf(hw * 1024.0f);
        const float ny2 = -y * y;
        float A0=0.f,B0=0.f,C0=0.f,D0=0.f;
        float A1=0.f,B1=0.f,C1=0.f,D1=0.f;
        float A2=0.f,B2=0.f,C2=0.f,D2=0.f;
        float A3=0.f,B3=0.f,C3=0.f,D3=0.f;

        #pragma unroll
        for (int k = 0; k < 2; k++) {
            int n = tid + k * 32;
            const float* W = (const float*)&sW[n];
            float er = W[2] + ny2;        // dw - y^2
            float ei = W[0] * y;          // cw * y
            float inv = frcp(er*er + ei*ei);
            float tr = er * inv, ti = ei * inv;
            const float* v;
            v = (const float*)&sV0[n];
            A0 += v[0]*tr; B0 += v[0]*ti; C0 += v[2]*tr; D0 += v[2]*ti;
            v = (const float*)&sV1[n];
            A1 += v[0]*tr; B1 += v[0]*ti; C1 += v[2]*tr; D1 += v[2]*ti;
            v = (const float*)&sV2[n];
            A2 += v[0]*tr; B2 += v[0]*ti; C2 += v[2]*tr; D2 += v[2]*ti;
            v = (const float*)&sV3[n];
            A3 += v[0]*tr; B3 += v[0]*ti; C3 += v[2]*tr; D3 += v[2]*ti;
        }
        #pragma unroll
        for (int off = 16; off > 0; off >>= 1) {
            A0 += __shfl_xor_sync(0xffffffffu, A0, off);
            B0 += __shfl_xor_sync(0xffffffffu, B0, off);
            C0 += __shfl_xor_sync(0xffffffffu, C0, off);
            D0 += __shfl_xor_sync(0xffffffffu, D0, off);
            A1 += __shfl_xor_sync(0xffffffffu, A1, off);
            B1 += __shfl_xor_sync(0xffffffffu, B1, off);
            C1 += __shfl_xor_sync(0xffffffffu, C1, off);
            D1 += __shfl_xor_sync(0xffffffffu, D1, off);
            A2 += __shfl_xor_sync(0xffffffffu, A2, off);
            B2 += __shfl_xor_sync(0xffffffffu, B2, off);
            C2 += __shfl_xor_sync(0xffffffffu, C2, off);
            D2 += __shfl_xor_sync(0xffffffffu, D2, off);
            A3 += __shfl_xor_sync(0xffffffffu, A3, off);
            B3 += __shfl_xor_sync(0xffffffffu, B3, off);
            C3 += __shfl_xor_sync(0xffffffffu, C3, off);
            D3 += __shfl_xor_sync(0xffffffffu, D3, off);
        }
        if (tid == 0) {
            float r00r = C0 + y*B0, r00i = y*A0 - D0;
            float r01r = C1 + y*B1, r01i = y*A1 - D1;
            float r10r = C2 + y*B2, r10i = y*A2 - D2;
            float r11r = C3 + y*B3, r11i = y*A3 - D3;
            float d11r = 1.0f + r11r, d11i = r11i;
            float dinv = frcp(d11r*d11r + d11i*d11i);
            float nr = r01r*r10r - r01i*r10i;
            float ni = r01r*r10i + r01i*r10r;
            float qr = (nr*d11r + ni*d11i) * dinv;
            float qi = (ni*d11r - nr*d11i) * dinv;
            float kr = r00r - qr, ki = r00i - qi;
            float y2 = 0.5f * y;
            skf[1024] = make_float2(kr - y2*ki, ki + y2*kr);
        }
    }
    __syncthreads();

    // ---------- phase 2: build Z (real-packed half-size spectrum) ----------
    // Z[m] = E + i*O; E=(K[m]+conj(K[M-m]))/2, O=e^{+i*pi*m/1024}*(K[m]-conj(K[M-m]))/2
    #pragma unroll
    for (int m = tid; m < M1024; m += NT) {
        float2 Ka = skf[m];
        float2 Kb = skf[M1024 - m];
        float Er = 0.5f * (Ka.x + Kb.x);
        float Ei = 0.5f * (Ka.y - Kb.y);
        float Fr = 0.5f * (Ka.x - Kb.x);
        float Fi = 0.5f * (Ka.y + Kb.y);
        float s, c;
        sincosf((float)(3.141592653589793 / 1024.0) * (float)m, &s, &c);
        float Or = c*Fr - s*Fi;
        float Oi = c*Fi + s*Fr;
        X[m] = make_float2(Er - Oi, Ei + Or);
    }
    __syncthreads();

    // ---------- phase 3: base-4 digit reversal (10 bits) ----------
    #pragma unroll
    for (int i = tid; i < M1024; i += NT) {
        unsigned r = __brev((unsigned)i) >> 22;
        r = ((r & 0x155u) << 1) | ((r >> 1) & 0x155u);
        if ((int)r > i) { float2 tswap = X[i]; X[i] = X[r]; X[r] = tswap; }
    }
    __syncthreads();

    // ---------- phase 4: 5 radix-4 DIT stages (inverse: +i); 256 butterflies ----------
    if (tid < 256) {
        float4 lo4 = *(const float4*)&X[4*tid];
        float4 hi4 = *(const float4*)&X[4*tid + 2];
        float2 a = make_float2(lo4.x, lo4.y), b = make_float2(lo4.z, lo4.w);
        float2 c = make_float2(hi4.x, hi4.y), d = make_float2(hi4.z, hi4.w);
        float2 apc = make_float2(a.x+c.x, a.y+c.y), amc = make_float2(a.x-c.x, a.y-c.y);
        float2 bpd = make_float2(b.x+d.x, b.y+d.y), bmd = make_float2(b.x-d.x, b.y-d.y);
        float2 y0 = make_float2(apc.x+bpd.x, apc.y+bpd.y);
        float2 y1 = make_float2(amc.x-bmd.y, amc.y+bmd.x);
        float2 y2 = make_float2(apc.x-bpd.x, apc.y-bpd.y);
        float2 y3 = make_float2(amc.x+bmd.y, amc.y-bmd.x);
        *(float4*)&X[4*tid]     = make_float4(y0.x, y0.y, y1.x, y1.y);
        *(float4*)&X[4*tid + 2] = make_float4(y2.x, y2.y, y3.x, y3.y);
    }
    __syncthreads();

    #pragma unroll
    for (int st = 1; st < 5; st++) {
        if (tid < 256) {
            int q = 1 << (2*st);
            int j = tid & (q - 1);
            int i0 = ((tid >> (2*st)) << (2*st + 2)) + j;
            float2 w1 = tw[j << (2*(4 - st))];
            float2 w2 = cmul(w1, w1);
            float2 w3 = cmul(w2, w1);

            float2 a = X[i0];
            float2 b = cmul(X[i0 + q],   w1);
            float2 c = cmul(X[i0 + 2*q], w2);
            float2 d = cmul(X[i0 + 3*q], w3);
            float2 apc = make_float2(a.x+c.x, a.y+c.y), amc = make_float2(a.x-c.x, a.y-c.y);
            float2 bpd = make_float2(b.x+d.x, b.y+d.y), bmd = make_float2(b.x-d.x, b.y-d.y);
            X[i0]       = make_float2(apc.x+bpd.x, apc.y+bpd.y);
            X[i0 + q]   = make_float2(amc.x-bmd.y, amc.y+bmd.x);
            X[i0 + 2*q] = make_float2(apc.x-bpd.x, apc.y-bpd.y);
            X[i0 + 3*q] = make_float2(amc.x+bmd.y, amc.y-bmd.x);
        }
        __syncthreads();
    }

    // ---------- phase 5: unpack to real output ----------
    const float sc = 1.0f / 1024.0f;
    float2* out2 = (float2*)(out + h * LFULL);
    #pragma unroll
    for (int t = tid; t < M1024; t += NT) {
        float2 z = X[t];
        out2[t] = make_float2(z.x * sc, z.y * sc);
    }
}

// ============================================================
extern "C" void kernel_launch(void* const* d_in, const int* in_sizes, int n_in,
                              void* d_out, int out_size)
{
    const float* C     = (const float*)d_in[0];   // (1,256,64,2)
    const float* B     = (const float*)d_in[1];   // (1,256,64,2)
    const float* P     = (const float*)d_in[2];   // (1,256,64,2)
    const float* iwr   = (const float*)d_in[3];   // (256,64)
    const float* wim   = (const float*)d_in[4];   // (256,64)
    const float* logdt = (const float*)d_in[5];   // (256,)
    (void)in_sizes; (void)n_in; (void)out_size;

    fused_kernel<<<HH, NT>>>(C, B, P, iwr, wim, logdt, (float*)d_out);
}